// round 1
// baseline (speedup 1.0000x reference)
#include <cuda_runtime.h>
#include <math.h>

#define Nn 20000
#define Ee 320000
#define Ll 16
#define Tt 64
#define Hh 128
#define Vv 32000
#define H3 384
#define NH (Nn*Hh)

// ---------------- scratch (static __device__ arrays; no allocation) ----------------
__device__ float g_xw[NH];
__device__ float g_agg[NH];
__device__ float g_h1[NH];
__device__ float g_pos[NH];
__device__ float g_dinv[Nn];
__device__ float g_E2[Vv*H3];
__device__ float g_gh[Nn*H3];
__device__ float g_h[NH];
__device__ float g_txt[NH];
__device__ float g_pre[Nn*768];

// ---------------- small kernels ----------------
__global__ void k_deg(const int* __restrict__ dst, float* __restrict__ deg) {
    int e = blockIdx.x * blockDim.x + threadIdx.x;
    if (e < Ee) atomicAdd(&deg[dst[e]], 1.0f);
}

__global__ void k_dinv(float* __restrict__ deg) {
    int n = blockIdx.x * blockDim.x + threadIdx.x;
    if (n < Nn) deg[n] = rsqrtf(deg[n] + 1.0f);
}

// xw = x[N,8] @ w[8,128]
__global__ void k_xw1(const float* __restrict__ x, const float* __restrict__ w,
                      float* __restrict__ out) {
    int n = blockIdx.x;
    int h = threadIdx.x;
    __shared__ float xs[8];
    if (threadIdx.x < 8) xs[threadIdx.x] = x[n * 8 + threadIdx.x];
    __syncthreads();
    float s = 0.f;
#pragma unroll
    for (int f = 0; f < 8; f++) s += xs[f] * w[f * 128 + h];
    out[n * 128 + h] = s;
}

// scatter: agg[dst] += xw[src] * dinv[src]*dinv[dst]   (one warp per edge)
__global__ void k_edge_agg(const int* __restrict__ src, const int* __restrict__ dst,
                           const float* __restrict__ dinv, const float* __restrict__ xw,
                           float* __restrict__ agg) {
    int idx = blockIdx.x * blockDim.x + threadIdx.x;
    int e = idx >> 5;
    int lane = idx & 31;
    if (e >= Ee) return;
    int s = src[e], d = dst[e];
    float norm = dinv[s] * dinv[d];
    float4 v = ((const float4*)(xw + (size_t)s * 128))[lane];
    float* ar = agg + (size_t)d * 128 + lane * 4;
    atomicAdd(ar + 0, v.x * norm);
    atomicAdd(ar + 1, v.y * norm);
    atomicAdd(ar + 2, v.z * norm);
    atomicAdd(ar + 3, v.w * norm);
}

// out = relu(agg + xw*dinv^2 + b)
__global__ void k_finish(const float* __restrict__ agg, const float* __restrict__ xw,
                         const float* __restrict__ dinv, const float* __restrict__ b,
                         float* __restrict__ out) {
    int idx = blockIdx.x * blockDim.x + threadIdx.x;
    if (idx >= NH) return;
    int n = idx >> 7, h = idx & 127;
    float di = dinv[n];
    float v = agg[idx] + xw[idx] * di * di + b[h];
    out[idx] = fmaxf(v, 0.f);
}

// GRU gate update for step t; txt += h_new
__global__ void k_gru(const int* __restrict__ xtext, const float* __restrict__ E2,
                      const float* __restrict__ gh, const float* __restrict__ bih,
                      const float* __restrict__ bhh, float* __restrict__ h,
                      float* __restrict__ txt, int t) {
    int idx = blockIdx.x * blockDim.x + threadIdx.x;
    if (idx >= NH) return;
    int n = idx >> 7, j = idx & 127;
    int tok = xtext[n * Ll + t];
    const float* e2 = E2 + (size_t)tok * H3;
    const float* g = gh + (size_t)n * H3;
    float gir = e2[j] + bih[j];
    float giz = e2[128 + j] + bih[128 + j];
    float gin = e2[256 + j] + bih[256 + j];
    float ghr = g[j] + bhh[j];
    float ghz = g[128 + j] + bhh[128 + j];
    float ghn = g[256 + j] + bhh[256 + j];
    float r = 1.f / (1.f + expf(-(gir + ghr)));
    float z = 1.f / (1.f + expf(-(giz + ghz)));
    float nn_ = tanhf(gin + r * ghn);
    float hp = h[idx];
    float h2 = (1.f - z) * nn_ + z * hp;
    h[idx] = h2;
    txt[idx] += h2;
}

// ---------------- generic 64x64 tiled fp32 GEMM ----------------
// C[M,Ncols] = A[M,K](lda) * B(ldb)   B either [K,Ncols] (NN) or [Ncols,K] (NT)
template <bool TRANSB>
__global__ void __launch_bounds__(256) gemm64(
    const float* __restrict__ A, int lda, const float* __restrict__ B, int ldb,
    float* __restrict__ C, int ldc, int M, int Ncols, int K) {
    __shared__ float As[16][65];
    __shared__ float Bs[16][65];
    int tid = threadIdx.x;
    int bm = blockIdx.x * 64;
    int bn = blockIdx.y * 64;
    int ty = tid >> 4, tx = tid & 15;
    float acc[4][4] = {};
    int am = tid >> 2;
    int ak = (tid & 3) * 4;
    for (int k0 = 0; k0 < K; k0 += 16) {
        float4 av = make_float4(0.f, 0.f, 0.f, 0.f);
        if (bm + am < M) av = *(const float4*)(A + (size_t)(bm + am) * lda + k0 + ak);
        As[ak + 0][am] = av.x; As[ak + 1][am] = av.y;
        As[ak + 2][am] = av.z; As[ak + 3][am] = av.w;
        if (TRANSB) {
            float4 bv = *(const float4*)(B + (size_t)(bn + am) * ldb + k0 + ak);
            Bs[ak + 0][am] = bv.x; Bs[ak + 1][am] = bv.y;
            Bs[ak + 2][am] = bv.z; Bs[ak + 3][am] = bv.w;
        } else {
            int bk = tid >> 4;
            int bnn = (tid & 15) * 4;
            float4 bv = *(const float4*)(B + (size_t)(k0 + bk) * ldb + bn + bnn);
            Bs[bk][bnn + 0] = bv.x; Bs[bk][bnn + 1] = bv.y;
            Bs[bk][bnn + 2] = bv.z; Bs[bk][bnn + 3] = bv.w;
        }
        __syncthreads();
#pragma unroll
        for (int k = 0; k < 16; k++) {
            float a0 = As[k][ty * 4 + 0], a1 = As[k][ty * 4 + 1];
            float a2 = As[k][ty * 4 + 2], a3 = As[k][ty * 4 + 3];
            float b0 = Bs[k][tx * 4 + 0], b1 = Bs[k][tx * 4 + 1];
            float b2 = Bs[k][tx * 4 + 2], b3 = Bs[k][tx * 4 + 3];
            acc[0][0] += a0 * b0; acc[0][1] += a0 * b1; acc[0][2] += a0 * b2; acc[0][3] += a0 * b3;
            acc[1][0] += a1 * b0; acc[1][1] += a1 * b1; acc[1][2] += a1 * b2; acc[1][3] += a1 * b3;
            acc[2][0] += a2 * b0; acc[2][1] += a2 * b1; acc[2][2] += a2 * b2; acc[2][3] += a2 * b3;
            acc[3][0] += a3 * b0; acc[3][1] += a3 * b1; acc[3][2] += a3 * b2; acc[3][3] += a3 * b3;
        }
        __syncthreads();
    }
#pragma unroll
    for (int i = 0; i < 4; i++) {
        int r = bm + ty * 4 + i;
        if (r < M) {
#pragma unroll
            for (int j = 0; j < 4; j++)
                C[(size_t)r * ldc + bn + tx * 4 + j] = acc[i][j];
        }
    }
}

// ---------------- fused per-edge: build e (relu of node-precomp sums),
// two head GEMMs (384->128), relu, 128->2, log_softmax ----------------
#define EH_SMEM ((64 * 129 + 2 * 128 * 128) * 4)

__global__ void __launch_bounds__(256) k_edge_heads(
    const int* __restrict__ src, const int* __restrict__ dst,
    const float* __restrict__ pre,
    const float* __restrict__ bpos, const float* __restrict__ btxt,
    const float* __restrict__ bimg,
    const float* __restrict__ rw1, const float* __restrict__ rb1,
    const float* __restrict__ rw2, const float* __restrict__ rb2,
    const float* __restrict__ cw1, const float* __restrict__ cb1,
    const float* __restrict__ cw2, const float* __restrict__ cb2,
    float* __restrict__ out) {
    extern __shared__ float sm[];
    float* As = sm;                 // 64 x 129
    float* Br = As + 64 * 129;      // 128 x 128
    float* Bc = Br + 128 * 128;     // 128 x 128
    __shared__ int ssrc[64];
    __shared__ int sdst[64];
    int tid = threadIdx.x;
    int e0 = blockIdx.x * 64;
    if (tid < 64) { ssrc[tid] = src[e0 + tid]; sdst[tid] = dst[e0 + tid]; }
    int ty = tid >> 4, tx = tid & 15;
    float accr[4][8] = {};
    float accc[4][8] = {};
    for (int c = 0; c < 3; c++) {
        const float* bias = (c == 0) ? bpos : ((c == 1) ? btxt : bimg);
        __syncthreads();
        // build A tile: 64 edges x 128 features of chunk c
#pragma unroll
        for (int l = 0; l < 32; l++) {
            int idx = tid + l * 256;
            int m = idx >> 7, k = idx & 127;
            int s = ssrc[m], d = sdst[m];
            float v = pre[(size_t)s * 768 + c * 256 + k] +
                      pre[(size_t)d * 768 + c * 256 + 128 + k] + bias[k];
            As[m * 129 + k] = fmaxf(v, 0.f);
        }
        // load both heads' W1 chunk (128x128 each)
#pragma unroll
        for (int l = 0; l < 16; l++) {
            int idx4 = tid + l * 256;
            int k = idx4 >> 5;
            int j = (idx4 & 31) * 4;
            *(float4*)&Br[k * 128 + j] = *(const float4*)(rw1 + (size_t)(c * 128 + k) * 128 + j);
            *(float4*)&Bc[k * 128 + j] = *(const float4*)(cw1 + (size_t)(c * 128 + k) * 128 + j);
        }
        __syncthreads();
#pragma unroll 4
        for (int k = 0; k < 128; k++) {
            float a[4];
#pragma unroll
            for (int i = 0; i < 4; i++) a[i] = As[(ty * 4 + i) * 129 + k];
            float4 br0 = *(float4*)&Br[k * 128 + tx * 8];
            float4 br1 = *(float4*)&Br[k * 128 + tx * 8 + 4];
            float4 bc0 = *(float4*)&Bc[k * 128 + tx * 8];
            float4 bc1 = *(float4*)&Bc[k * 128 + tx * 8 + 4];
#pragma unroll
            for (int i = 0; i < 4; i++) {
                accr[i][0] += a[i] * br0.x; accr[i][1] += a[i] * br0.y;
                accr[i][2] += a[i] * br0.z; accr[i][3] += a[i] * br0.w;
                accr[i][4] += a[i] * br1.x; accr[i][5] += a[i] * br1.y;
                accr[i][6] += a[i] * br1.z; accr[i][7] += a[i] * br1.w;
                accc[i][0] += a[i] * bc0.x; accc[i][1] += a[i] * bc0.y;
                accc[i][2] += a[i] * bc0.z; accc[i][3] += a[i] * bc0.w;
                accc[i][4] += a[i] * bc1.x; accc[i][5] += a[i] * bc1.y;
                accc[i][6] += a[i] * bc1.z; accc[i][7] += a[i] * bc1.w;
            }
        }
    }
    // epilogue: relu(+b1), project to 2 classes, reduce across tx, log_softmax
    float pr0[4] = {}, pr1[4] = {}, pc0[4] = {}, pc1[4] = {};
#pragma unroll
    for (int j = 0; j < 8; j++) {
        int jj = tx * 8 + j;
        float rb = rb1[jj], cb = cb1[jj];
        float rw20 = rw2[jj * 2], rw21 = rw2[jj * 2 + 1];
        float cw20 = cw2[jj * 2], cw21 = cw2[jj * 2 + 1];
#pragma unroll
        for (int i = 0; i < 4; i++) {
            float hr = fmaxf(accr[i][j] + rb, 0.f);
            pr0[i] += hr * rw20;
            pr1[i] += hr * rw21;
            float hc = fmaxf(accc[i][j] + cb, 0.f);
            pc0[i] += hc * cw20;
            pc1[i] += hc * cw21;
        }
    }
#pragma unroll
    for (int off = 8; off >= 1; off >>= 1) {
#pragma unroll
        for (int i = 0; i < 4; i++) {
            pr0[i] += __shfl_down_sync(0xffffffffu, pr0[i], off, 16);
            pr1[i] += __shfl_down_sync(0xffffffffu, pr1[i], off, 16);
            pc0[i] += __shfl_down_sync(0xffffffffu, pc0[i], off, 16);
            pc1[i] += __shfl_down_sync(0xffffffffu, pc1[i], off, 16);
        }
    }
    if (tx == 0) {
        float rb20 = rb2[0], rb21 = rb2[1], cb20 = cb2[0], cb21 = cb2[1];
#pragma unroll
        for (int i = 0; i < 4; i++) {
            int e = e0 + ty * 4 + i;
            float l0 = pr0[i] + rb20, l1 = pr1[i] + rb21;
            float mx = fmaxf(l0, l1);
            float lse = mx + logf(expf(l0 - mx) + expf(l1 - mx));
            out[(size_t)e * 2 + 0] = l0 - lse;
            out[(size_t)e * 2 + 1] = l1 - lse;
            l0 = pc0[i] + cb20; l1 = pc1[i] + cb21;
            mx = fmaxf(l0, l1);
            lse = mx + logf(expf(l0 - mx) + expf(l1 - mx));
            out[(size_t)(Ee + e) * 2 + 0] = l0 - lse;
            out[(size_t)(Ee + e) * 2 + 1] = l1 - lse;
        }
    }
}

// ---------------- launch ----------------
extern "C" void kernel_launch(void* const* d_in, const int* in_sizes, int n_in,
                              void* d_out, int out_size) {
    const float* x     = (const float*)d_in[0];
    const int*   ei    = (const int*)d_in[1];
    const int*   xtext = (const int*)d_in[2];
    const float* img   = (const float*)d_in[3];
    const float* c1w   = (const float*)d_in[4];
    const float* c1b   = (const float*)d_in[5];
    const float* c2w   = (const float*)d_in[6];
    const float* c2b   = (const float*)d_in[7];
    const float* emb   = (const float*)d_in[8];
    const float* wih   = (const float*)d_in[9];
    const float* whh   = (const float*)d_in[10];
    const float* bih   = (const float*)d_in[11];
    const float* bhh   = (const float*)d_in[12];
    const float* lpw   = (const float*)d_in[13];
    const float* lpb   = (const float*)d_in[14];
    const float* ltw   = (const float*)d_in[15];
    const float* ltb   = (const float*)d_in[16];
    const float* liw   = (const float*)d_in[17];
    const float* lib   = (const float*)d_in[18];
    const float* rw1   = (const float*)d_in[19];
    const float* rb1   = (const float*)d_in[20];
    const float* rw2   = (const float*)d_in[21];
    const float* rb2   = (const float*)d_in[22];
    const float* cw1   = (const float*)d_in[23];
    const float* cb1   = (const float*)d_in[24];
    const float* cw2   = (const float*)d_in[25];
    const float* cb2   = (const float*)d_in[26];
    float* out = (float*)d_out;
    const int* srcp = ei;
    const int* dstp = ei + Ee;

    float *p_xw, *p_agg, *p_h1, *p_pos, *p_dinv, *p_E2, *p_gh, *p_h, *p_txt, *p_pre;
    cudaGetSymbolAddress((void**)&p_xw, g_xw);
    cudaGetSymbolAddress((void**)&p_agg, g_agg);
    cudaGetSymbolAddress((void**)&p_h1, g_h1);
    cudaGetSymbolAddress((void**)&p_pos, g_pos);
    cudaGetSymbolAddress((void**)&p_dinv, g_dinv);
    cudaGetSymbolAddress((void**)&p_E2, g_E2);
    cudaGetSymbolAddress((void**)&p_gh, g_gh);
    cudaGetSymbolAddress((void**)&p_h, g_h);
    cudaGetSymbolAddress((void**)&p_txt, g_txt);
    cudaGetSymbolAddress((void**)&p_pre, g_pre);

    // degree / dinv
    cudaMemsetAsync(p_dinv, 0, Nn * sizeof(float));
    k_deg<<<(Ee + 255) / 256, 256>>>(dstp, p_dinv);
    k_dinv<<<(Nn + 255) / 256, 256>>>(p_dinv);

    // GCN layer 1
    k_xw1<<<Nn, 128>>>(x, c1w, p_xw);
    cudaMemsetAsync(p_agg, 0, (size_t)NH * sizeof(float));
    k_edge_agg<<<(Ee * 32) / 256, 256>>>(srcp, dstp, p_dinv, p_xw, p_agg);
    k_finish<<<(NH + 255) / 256, 256>>>(p_agg, p_xw, p_dinv, c1b, p_h1);

    // GCN layer 2
    {
        dim3 g((Nn + 63) / 64, 2);
        gemm64<false><<<g, 256>>>(p_h1, 128, c2w, 128, p_xw, 128, Nn, 128, 128);
    }
    cudaMemsetAsync(p_agg, 0, (size_t)NH * sizeof(float));
    k_edge_agg<<<(Ee * 32) / 256, 256>>>(srcp, dstp, p_dinv, p_xw, p_agg);
    k_finish<<<(NH + 255) / 256, 256>>>(p_agg, p_xw, p_dinv, c2b, p_pos);

    // GRU: precompute vocab-level input projection E2 = embed @ wih^T
    {
        dim3 g((Vv + 63) / 64, H3 / 64);
        gemm64<true><<<g, 256>>>(emb, Tt, wih, Tt, p_E2, H3, Vv, H3, Tt);
    }
    cudaMemsetAsync(p_h, 0, (size_t)NH * sizeof(float));
    cudaMemsetAsync(p_txt, 0, (size_t)NH * sizeof(float));
    for (int t = 0; t < Ll; t++) {
        dim3 g((Nn + 63) / 64, H3 / 64);
        gemm64<true><<<g, 256>>>(p_h, Hh, whh, Hh, p_gh, H3, Nn, H3, Hh);
        k_gru<<<(NH + 255) / 256, 256>>>(xtext, p_E2, p_gh, bih, bhh, p_h, p_txt, t);
    }

    // per-node precomputed edge-linear halves -> g_pre[N,768]
    {
        dim3 g((Nn + 63) / 64, 2);
        gemm64<false><<<g, 256>>>(p_pos, 128, lpw, 128, p_pre + 0, 768, Nn, 128, 128);
        gemm64<false><<<g, 256>>>(p_pos, 128, lpw + 128 * 128, 128, p_pre + 128, 768, Nn, 128, 128);
        gemm64<false><<<g, 256>>>(p_txt, 128, ltw, 128, p_pre + 256, 768, Nn, 128, 128);
        gemm64<false><<<g, 256>>>(p_txt, 128, ltw + 128 * 128, 128, p_pre + 384, 768, Nn, 128, 128);
        gemm64<false><<<g, 256>>>(img, 256, liw, 128, p_pre + 512, 768, Nn, 128, 256);
        gemm64<false><<<g, 256>>>(img, 256, liw + 256 * 128, 128, p_pre + 640, 768, Nn, 128, 256);
    }

    // fused edge heads
    cudaFuncSetAttribute(k_edge_heads, cudaFuncAttributeMaxDynamicSharedMemorySize, EH_SMEM);
    k_edge_heads<<<Ee / 64, 256, EH_SMEM>>>(srcp, dstp, p_pre, lpb, ltb, lib,
                                            rw1, rb1, rw2, rb2, cw1, cb1, cw2, cb2, out);
    (void)in_sizes; (void)n_in; (void)out_size;
}

// round 2
// speedup vs baseline: 2.4395x; 2.4395x over previous
#include <cuda_runtime.h>
#include <math.h>

#define Nn 20000
#define Ee 320000
#define Ll 16
#define Tt 64
#define Hh 128
#define Vv 32000
#define H3 384
#define NH (Nn*Hh)

// ---------------- scratch ----------------
__device__ float g_xw[NH];
__device__ float g_agg[NH];
__device__ float g_h1[NH];
__device__ float g_pos[NH];
__device__ float g_dinv[Nn];
__device__ float g_E2[Vv*H3];
__device__ float g_gh[Nn*H3];
__device__ float g_h[NH];
__device__ float g_txt[NH];
__device__ float g_pre[Nn*768];

// ---------------- tf32 helpers ----------------
__device__ __forceinline__ float f2tf(float x) {
    unsigned u;
    asm("cvt.rna.tf32.f32 %0, %1;" : "=r"(u) : "f"(x));
    return __uint_as_float(u);
}

__device__ __forceinline__ void mma_tf32(float* d, const unsigned* a, const unsigned* b) {
    asm volatile(
        "mma.sync.aligned.m16n8k8.row.col.f32.tf32.tf32.f32 "
        "{%0,%1,%2,%3},{%4,%5,%6,%7},{%8,%9},{%0,%1,%2,%3};"
        : "+f"(d[0]), "+f"(d[1]), "+f"(d[2]), "+f"(d[3])
        : "r"(a[0]), "r"(a[1]), "r"(a[2]), "r"(a[3]), "r"(b[0]), "r"(b[1]));
}

// ---------------- small kernels ----------------
__global__ void k_deg(const int* __restrict__ dst, float* __restrict__ deg) {
    int e = blockIdx.x * blockDim.x + threadIdx.x;
    if (e < Ee) atomicAdd(&deg[dst[e]], 1.0f);
}

__global__ void k_dinv(float* __restrict__ deg) {
    int n = blockIdx.x * blockDim.x + threadIdx.x;
    if (n < Nn) deg[n] = rsqrtf(deg[n] + 1.0f);
}

__global__ void k_xw1(const float* __restrict__ x, const float* __restrict__ w,
                      float* __restrict__ out) {
    int n = blockIdx.x;
    int h = threadIdx.x;
    __shared__ float xs[8];
    if (threadIdx.x < 8) xs[threadIdx.x] = x[n * 8 + threadIdx.x];
    __syncthreads();
    float s = 0.f;
#pragma unroll
    for (int f = 0; f < 8; f++) s += xs[f] * w[f * 128 + h];
    out[n * 128 + h] = s;
}

__global__ void k_edge_agg(const int* __restrict__ src, const int* __restrict__ dst,
                           const float* __restrict__ dinv, const float* __restrict__ xw,
                           float* __restrict__ agg) {
    int idx = blockIdx.x * blockDim.x + threadIdx.x;
    int e = idx >> 5;
    int lane = idx & 31;
    if (e >= Ee) return;
    int s = src[e], d = dst[e];
    float norm = dinv[s] * dinv[d];
    float4 v = ((const float4*)(xw + (size_t)s * 128))[lane];
    float* ar = agg + (size_t)d * 128 + lane * 4;
    atomicAdd(ar + 0, v.x * norm);
    atomicAdd(ar + 1, v.y * norm);
    atomicAdd(ar + 2, v.z * norm);
    atomicAdd(ar + 3, v.w * norm);
}

__global__ void k_finish(const float* __restrict__ agg, const float* __restrict__ xw,
                         const float* __restrict__ dinv, const float* __restrict__ b,
                         float* __restrict__ out) {
    int idx = blockIdx.x * blockDim.x + threadIdx.x;
    if (idx >= NH) return;
    int n = idx >> 7, h = idx & 127;
    float di = dinv[n];
    float v = agg[idx] + xw[idx] * di * di + b[h];
    out[idx] = fmaxf(v, 0.f);
}

__global__ void k_gru(const int* __restrict__ xtext, const float* __restrict__ E2,
                      const float* __restrict__ gh, const float* __restrict__ bih,
                      const float* __restrict__ bhh, float* __restrict__ h,
                      float* __restrict__ txt, int t) {
    int idx = blockIdx.x * blockDim.x + threadIdx.x;
    if (idx >= NH) return;
    int n = idx >> 7, j = idx & 127;
    int tok = xtext[n * Ll + t];
    const float* e2 = E2 + (size_t)tok * H3;
    const float* g = gh + (size_t)n * H3;
    float gir = e2[j] + bih[j];
    float giz = e2[128 + j] + bih[128 + j];
    float gin = e2[256 + j] + bih[256 + j];
    float ghr = g[j] + bhh[j];
    float ghz = g[128 + j] + bhh[128 + j];
    float ghn = g[256 + j] + bhh[256 + j];
    float r = 1.f / (1.f + expf(-(gir + ghr)));
    float z = 1.f / (1.f + expf(-(giz + ghz)));
    float nn_ = tanhf(gin + r * ghn);
    float hp = h[idx];
    float h2 = (1.f - z) * nn_ + z * hp;
    h[idx] = h2;
    txt[idx] += h2;
}

// ---------------- generic tf32 tensor-core GEMM ----------------
// C[M,N] = A[M,K] @ B    NT: B is [N,K] row-major (B^T),  NN: B is [K,N] row-major.
// Tile: 64 x 128, K-tile 32. Requires N multiple of 128 per grid.y sizing, K % 32 == 0.
template <bool NT>
__global__ void __launch_bounds__(256) gemm_tf32(
    const float* __restrict__ A, int lda, const float* __restrict__ B, int ldb,
    float* __restrict__ C, int ldc, int M, int N, int K) {
    __shared__ float As[64 * 36];
    __shared__ float Bs[5120];   // NT: 128x40, NN: 32x136
    int tid = threadIdx.x;
    int w = tid >> 5;
    int lane = tid & 31;
    int ly = lane >> 2, lx = lane & 3;
    int bm = blockIdx.x * 64, bn = blockIdx.y * 128;
    float acc[4][2][4];
#pragma unroll
    for (int i = 0; i < 4; i++)
#pragma unroll
        for (int j = 0; j < 2; j++)
#pragma unroll
            for (int q = 0; q < 4; q++) acc[i][j][q] = 0.f;

    for (int kt = 0; kt < K; kt += 32) {
#pragma unroll
        for (int l = 0; l < 2; l++) {
            int li = tid + l * 256;
            int row = li >> 3;
            int kc = (li & 7) * 4;
            float4 v = make_float4(0.f, 0.f, 0.f, 0.f);
            if (bm + row < M) v = *(const float4*)(A + (size_t)(bm + row) * lda + kt + kc);
            float4 t;
            t.x = f2tf(v.x); t.y = f2tf(v.y); t.z = f2tf(v.z); t.w = f2tf(v.w);
            *(float4*)&As[row * 36 + kc] = t;
        }
        if (NT) {
#pragma unroll
            for (int l = 0; l < 4; l++) {
                int li = tid + l * 256;
                int n = li >> 3;
                int kc = (li & 7) * 4;
                float4 v = *(const float4*)(B + (size_t)(bn + n) * ldb + kt + kc);
                float4 t;
                t.x = f2tf(v.x); t.y = f2tf(v.y); t.z = f2tf(v.z); t.w = f2tf(v.w);
                *(float4*)&Bs[n * 40 + kc] = t;
            }
        } else {
#pragma unroll
            for (int l = 0; l < 4; l++) {
                int li = tid + l * 256;
                int k = li >> 5;
                int nc = (li & 31) * 4;
                float4 v = *(const float4*)(B + (size_t)(kt + k) * ldb + bn + nc);
                float4 t;
                t.x = f2tf(v.x); t.y = f2tf(v.y); t.z = f2tf(v.z); t.w = f2tf(v.w);
                *(float4*)&Bs[k * 136 + nc] = t;
            }
        }
        __syncthreads();
#pragma unroll
        for (int kk = 0; kk < 4; kk++) {
            unsigned a[4][4];
#pragma unroll
            for (int mt = 0; mt < 4; mt++) {
                int row = mt * 16 + ly;
                int k = kk * 8 + lx;
                a[mt][0] = __float_as_uint(As[row * 36 + k]);
                a[mt][1] = __float_as_uint(As[(row + 8) * 36 + k]);
                a[mt][2] = __float_as_uint(As[row * 36 + k + 4]);
                a[mt][3] = __float_as_uint(As[(row + 8) * 36 + k + 4]);
            }
            unsigned b[2][2];
#pragma unroll
            for (int nt = 0; nt < 2; nt++) {
                int n = w * 16 + nt * 8 + ly;
                int k = kk * 8 + lx;
                if (NT) {
                    b[nt][0] = __float_as_uint(Bs[n * 40 + k]);
                    b[nt][1] = __float_as_uint(Bs[n * 40 + k + 4]);
                } else {
                    b[nt][0] = __float_as_uint(Bs[k * 136 + n]);
                    b[nt][1] = __float_as_uint(Bs[(k + 4) * 136 + n]);
                }
            }
#pragma unroll
            for (int mt = 0; mt < 4; mt++)
#pragma unroll
                for (int nt = 0; nt < 2; nt++) mma_tf32(acc[mt][nt], a[mt], b[nt]);
        }
        __syncthreads();
    }
#pragma unroll
    for (int mt = 0; mt < 4; mt++)
#pragma unroll
        for (int nt = 0; nt < 2; nt++) {
            int row = bm + mt * 16 + ly;
            int col = bn + w * 16 + nt * 8 + lx * 2;
            if (row < M) {
                C[(size_t)row * ldc + col] = acc[mt][nt][0];
                C[(size_t)row * ldc + col + 1] = acc[mt][nt][1];
            }
            if (row + 8 < M) {
                C[(size_t)(row + 8) * ldc + col] = acc[mt][nt][2];
                C[(size_t)(row + 8) * ldc + col + 1] = acc[mt][nt][3];
            }
        }
}

// ---------------- fused edge heads (tf32 mma) ----------------
// smem: As 64x132 | Wr 64x136 | Wc 64x136 | red 2x4x64x2
#define EH_AS   (64 * 132)
#define EH_W    (64 * 136)
#define EH_RED  (2 * 4 * 64 * 2)
#define EH_SMEM ((EH_AS + 2 * EH_W + EH_RED) * 4)

__global__ void __launch_bounds__(256) k_edge_heads_tf32(
    const int* __restrict__ src, const int* __restrict__ dst,
    const float* __restrict__ pre,
    const float* __restrict__ bpos, const float* __restrict__ btxt,
    const float* __restrict__ bimg,
    const float* __restrict__ rw1, const float* __restrict__ rb1,
    const float* __restrict__ rw2, const float* __restrict__ rb2,
    const float* __restrict__ cw1, const float* __restrict__ cb1,
    const float* __restrict__ cw2, const float* __restrict__ cb2,
    float* __restrict__ out) {
    extern __shared__ float sm[];
    float* As = sm;                  // [64][132]
    float* Wr = As + EH_AS;          // [64][136]  (k-local x n)
    float* Wc = Wr + EH_W;
    float* red = Wc + EH_W;          // [2][4][64][2]
    __shared__ int ssrc[64];
    __shared__ int sdst[64];
    int tid = threadIdx.x;
    int w = tid >> 5;
    int lane = tid & 31;
    int ly = lane >> 2, lx = lane & 3;
    int head = w & 1;                // 0 = row head, 1 = col head
    int q = w >> 1;                  // n-quarter
    int n0 = q * 32;
    int e0 = blockIdx.x * 64;
    if (tid < 64) { ssrc[tid] = src[e0 + tid]; sdst[tid] = dst[e0 + tid]; }

    float acc[4][4][4];
#pragma unroll
    for (int i = 0; i < 4; i++)
#pragma unroll
        for (int j = 0; j < 4; j++)
#pragma unroll
            for (int p = 0; p < 4; p++) acc[i][j][p] = 0.f;

    const float* W1h = head ? cw1 : rw1;

    for (int c = 0; c < 3; c++) {
        const float* bias = (c == 0) ? bpos : ((c == 1) ? btxt : bimg);
        __syncthreads();
        // build A tile: 64 edges x 128 feats of chunk c
#pragma unroll
        for (int l = 0; l < 32; l++) {
            int idx = tid + l * 256;
            int m = idx >> 7, k = idx & 127;
            int s = ssrc[m], d = sdst[m];
            float v = pre[(size_t)s * 768 + c * 256 + k] +
                      pre[(size_t)d * 768 + c * 256 + 128 + k] + bias[k];
            As[m * 132 + k] = f2tf(fmaxf(v, 0.f));
        }
        for (int half = 0; half < 2; half++) {
            __syncthreads();
            // load both heads' W1 half-chunk [64 k][128 n]
#pragma unroll
            for (int l = 0; l < 8; l++) {
                int li = tid + l * 256;
                int r = li >> 5;
                int nc = (li & 31) * 4;
                size_t go = (size_t)(c * 128 + half * 64 + r) * 128 + nc;
                float4 v = *(const float4*)(rw1 + go);
                float4 t;
                t.x = f2tf(v.x); t.y = f2tf(v.y); t.z = f2tf(v.z); t.w = f2tf(v.w);
                *(float4*)&Wr[r * 136 + nc] = t;
                v = *(const float4*)(cw1 + go);
                t.x = f2tf(v.x); t.y = f2tf(v.y); t.z = f2tf(v.z); t.w = f2tf(v.w);
                *(float4*)&Wc[r * 136 + nc] = t;
            }
            __syncthreads();
            const float* Wh = head ? Wc : Wr;
#pragma unroll
            for (int kk = 0; kk < 8; kk++) {
                unsigned a[4][4];
#pragma unroll
                for (int mt = 0; mt < 4; mt++) {
                    int row = mt * 16 + ly;
                    int k = half * 64 + kk * 8 + lx;
                    a[mt][0] = __float_as_uint(As[row * 132 + k]);
                    a[mt][1] = __float_as_uint(As[(row + 8) * 132 + k]);
                    a[mt][2] = __float_as_uint(As[row * 132 + k + 4]);
                    a[mt][3] = __float_as_uint(As[(row + 8) * 132 + k + 4]);
                }
                unsigned b[4][2];
#pragma unroll
                for (int nt = 0; nt < 4; nt++) {
                    int n = n0 + nt * 8 + ly;
                    int kb = kk * 8 + lx;
                    b[nt][0] = __float_as_uint(Wh[kb * 136 + n]);
                    b[nt][1] = __float_as_uint(Wh[(kb + 4) * 136 + n]);
                }
#pragma unroll
                for (int mt = 0; mt < 4; mt++)
#pragma unroll
                    for (int nt = 0; nt < 4; nt++) mma_tf32(acc[mt][nt], a[mt], b[nt]);
            }
        }
    }
    (void)W1h;

    // epilogue: relu(+b1), project to 2 classes, reduce
    const float* b1 = head ? cb1 : rb1;
    const float* w2 = head ? cw2 : rw2;
    float p[4][2][2];
#pragma unroll
    for (int mt = 0; mt < 4; mt++)
#pragma unroll
        for (int rr = 0; rr < 2; rr++) { p[mt][rr][0] = 0.f; p[mt][rr][1] = 0.f; }
#pragma unroll
    for (int nt = 0; nt < 4; nt++) {
        int j0 = n0 + nt * 8 + lx * 2;
        float b10 = b1[j0], b11 = b1[j0 + 1];
        float w200 = w2[j0 * 2], w201 = w2[j0 * 2 + 1];
        float w210 = w2[(j0 + 1) * 2], w211 = w2[(j0 + 1) * 2 + 1];
#pragma unroll
        for (int mt = 0; mt < 4; mt++) {
            float h0 = fmaxf(acc[mt][nt][0] + b10, 0.f);
            float h1 = fmaxf(acc[mt][nt][1] + b11, 0.f);
            float h2 = fmaxf(acc[mt][nt][2] + b10, 0.f);
            float h3 = fmaxf(acc[mt][nt][3] + b11, 0.f);
            p[mt][0][0] += h0 * w200 + h1 * w210;
            p[mt][0][1] += h0 * w201 + h1 * w211;
            p[mt][1][0] += h2 * w200 + h3 * w210;
            p[mt][1][1] += h2 * w201 + h3 * w211;
        }
    }
#pragma unroll
    for (int mt = 0; mt < 4; mt++)
#pragma unroll
        for (int rr = 0; rr < 2; rr++)
#pragma unroll
            for (int cl = 0; cl < 2; cl++) {
                float v = p[mt][rr][cl];
                v += __shfl_down_sync(0xffffffffu, v, 2, 4);
                v += __shfl_down_sync(0xffffffffu, v, 1, 4);
                p[mt][rr][cl] = v;
            }
    if (lx == 0) {
#pragma unroll
        for (int mt = 0; mt < 4; mt++)
#pragma unroll
            for (int rr = 0; rr < 2; rr++) {
                int row = mt * 16 + ly + rr * 8;
                red[((head * 4 + q) * 64 + row) * 2 + 0] = p[mt][rr][0];
                red[((head * 4 + q) * 64 + row) * 2 + 1] = p[mt][rr][1];
            }
    }
    __syncthreads();
    if (tid < 128) {
        int m = tid & 63;
        int h = tid >> 6;
        float l0 = 0.f, l1 = 0.f;
#pragma unroll
        for (int qq = 0; qq < 4; qq++) {
            l0 += red[((h * 4 + qq) * 64 + m) * 2 + 0];
            l1 += red[((h * 4 + qq) * 64 + m) * 2 + 1];
        }
        const float* b2 = h ? cb2 : rb2;
        l0 += b2[0];
        l1 += b2[1];
        float mx = fmaxf(l0, l1);
        float lse = mx + logf(expf(l0 - mx) + expf(l1 - mx));
        size_t base = ((size_t)h * Ee + e0 + m) * 2;
        out[base + 0] = l0 - lse;
        out[base + 1] = l1 - lse;
    }
}

// ---------------- launch ----------------
extern "C" void kernel_launch(void* const* d_in, const int* in_sizes, int n_in,
                              void* d_out, int out_size) {
    const float* x     = (const float*)d_in[0];
    const int*   ei    = (const int*)d_in[1];
    const int*   xtext = (const int*)d_in[2];
    const float* img   = (const float*)d_in[3];
    const float* c1w   = (const float*)d_in[4];
    const float* c1b   = (const float*)d_in[5];
    const float* c2w   = (const float*)d_in[6];
    const float* c2b   = (const float*)d_in[7];
    const float* emb   = (const float*)d_in[8];
    const float* wih   = (const float*)d_in[9];
    const float* whh   = (const float*)d_in[10];
    const float* bih   = (const float*)d_in[11];
    const float* bhh   = (const float*)d_in[12];
    const float* lpw   = (const float*)d_in[13];
    const float* lpb   = (const float*)d_in[14];
    const float* ltw   = (const float*)d_in[15];
    const float* ltb   = (const float*)d_in[16];
    const float* liw   = (const float*)d_in[17];
    const float* lib   = (const float*)d_in[18];
    const float* rw1   = (const float*)d_in[19];
    const float* rb1   = (const float*)d_in[20];
    const float* rw2   = (const float*)d_in[21];
    const float* rb2   = (const float*)d_in[22];
    const float* cw1   = (const float*)d_in[23];
    const float* cb1   = (const float*)d_in[24];
    const float* cw2   = (const float*)d_in[25];
    const float* cb2   = (const float*)d_in[26];
    float* out = (float*)d_out;
    const int* srcp = ei;
    const int* dstp = ei + Ee;

    float *p_xw, *p_agg, *p_h1, *p_pos, *p_dinv, *p_E2, *p_gh, *p_h, *p_txt, *p_pre;
    cudaGetSymbolAddress((void**)&p_xw, g_xw);
    cudaGetSymbolAddress((void**)&p_agg, g_agg);
    cudaGetSymbolAddress((void**)&p_h1, g_h1);
    cudaGetSymbolAddress((void**)&p_pos, g_pos);
    cudaGetSymbolAddress((void**)&p_dinv, g_dinv);
    cudaGetSymbolAddress((void**)&p_E2, g_E2);
    cudaGetSymbolAddress((void**)&p_gh, g_gh);
    cudaGetSymbolAddress((void**)&p_h, g_h);
    cudaGetSymbolAddress((void**)&p_txt, g_txt);
    cudaGetSymbolAddress((void**)&p_pre, g_pre);

    // degree / dinv
    cudaMemsetAsync(p_dinv, 0, Nn * sizeof(float));
    k_deg<<<(Ee + 255) / 256, 256>>>(dstp, p_dinv);
    k_dinv<<<(Nn + 255) / 256, 256>>>(p_dinv);

    // GCN layer 1
    k_xw1<<<Nn, 128>>>(x, c1w, p_xw);
    cudaMemsetAsync(p_agg, 0, (size_t)NH * sizeof(float));
    k_edge_agg<<<(Ee * 32) / 256, 256>>>(srcp, dstp, p_dinv, p_xw, p_agg);
    k_finish<<<(NH + 255) / 256, 256>>>(p_agg, p_xw, p_dinv, c1b, p_h1);

    // GCN layer 2 (NN: C = h1 @ c2w)
    {
        dim3 g((Nn + 63) / 64, 1);
        gemm_tf32<false><<<g, 256>>>(p_h1, 128, c2w, 128, p_xw, 128, Nn, 128, 128);
    }
    cudaMemsetAsync(p_agg, 0, (size_t)NH * sizeof(float));
    k_edge_agg<<<(Ee * 32) / 256, 256>>>(srcp, dstp, p_dinv, p_xw, p_agg);
    k_finish<<<(NH + 255) / 256, 256>>>(p_agg, p_xw, p_dinv, c2b, p_pos);

    // GRU: E2 = embed @ wih^T   (NT)
    {
        dim3 g((Vv + 63) / 64, H3 / 128);
        gemm_tf32<true><<<g, 256>>>(emb, Tt, wih, Tt, p_E2, H3, Vv, H3, Tt);
    }
    cudaMemsetAsync(p_h, 0, (size_t)NH * sizeof(float));
    cudaMemsetAsync(p_txt, 0, (size_t)NH * sizeof(float));
    for (int t = 0; t < Ll; t++) {
        dim3 g((Nn + 63) / 64, H3 / 128);
        gemm_tf32<true><<<g, 256>>>(p_h, Hh, whh, Hh, p_gh, H3, Nn, H3, Hh);
        k_gru<<<(NH + 255) / 256, 256>>>(xtext, p_E2, p_gh, bih, bhh, p_h, p_txt, t);
    }

    // per-node precomputed edge-linear halves -> g_pre[N,768]  (NN)
    {
        dim3 g((Nn + 63) / 64, 1);
        gemm_tf32<false><<<g, 256>>>(p_pos, 128, lpw, 128, p_pre + 0, 768, Nn, 128, 128);
        gemm_tf32<false><<<g, 256>>>(p_pos, 128, lpw + 128 * 128, 128, p_pre + 128, 768, Nn, 128, 128);
        gemm_tf32<false><<<g, 256>>>(p_txt, 128, ltw, 128, p_pre + 256, 768, Nn, 128, 128);
        gemm_tf32<false><<<g, 256>>>(p_txt, 128, ltw + 128 * 128, 128, p_pre + 384, 768, Nn, 128, 128);
        gemm_tf32<false><<<g, 256>>>(img, 256, liw, 128, p_pre + 512, 768, Nn, 128, 256);
        gemm_tf32<false><<<g, 256>>>(img, 256, liw + 256 * 128, 128, p_pre + 640, 768, Nn, 128, 256);
    }

    // fused edge heads (tf32 tensor cores)
    cudaFuncSetAttribute(k_edge_heads_tf32, cudaFuncAttributeMaxDynamicSharedMemorySize, EH_SMEM);
    k_edge_heads_tf32<<<Ee / 64, 256, EH_SMEM>>>(srcp, dstp, p_pre, lpb, ltb, lib,
                                                 rw1, rb1, rw2, rb2, cw1, cb1, cw2, cb2, out);
    (void)in_sizes; (void)n_in; (void)out_size;
}